// round 13
// baseline (speedup 1.0000x reference)
#include <cuda_runtime.h>
#include <cuda_bf16.h>
#include <cstdint>

// ---------------------------------------------------------------------------
// DGCNN segmentation forward.  B=8, C=3, N=4096, K=20, emb=1024, ncls=13.
// Internal layout: row-major (B*N, C) feature matrices.
// ---------------------------------------------------------------------------

#define BATCH 8
#define NPTS  4096
#define M_ALL (BATCH * NPTS)   // 32768
#define KNN_K 20
#define RSQ   0.99999500003749968f   // 1/sqrt(1+1e-5)
#define SLOPE 0.2f

// Scratch (device globals; no allocation allowed)
__device__ float d_F[(size_t)M_ALL * 192];      // [x1 | x2 | x3]
__device__ float d_A[(size_t)M_ALL * 64];
__device__ float d_C[(size_t)M_ALL * 64];
__device__ int   d_idx[(size_t)M_ALL * KNN_K];
__device__ float d_nrm[M_ALL];
__device__ float d_gmax[BATCH * 1024];
__device__ float d_bias7[BATCH * 512];
__device__ float d_buf7[(size_t)M_ALL * 512];
__device__ float d_buf8[(size_t)M_ALL * 256];
__device__ float d_buf9[(size_t)M_ALL * 128];

__device__ __forceinline__ float leaky(float v) { return v > 0.f ? v : SLOPE * v; }

__device__ __forceinline__ void atomicMaxF(float* addr, float v) {
    int* ai = (int*)addr;
    int old = *ai;
    while (__int_as_float(old) < v) {
        int assumed = old;
        old = atomicCAS(ai, assumed, __float_as_int(v));
        if (old == assumed) break;
    }
}

__device__ __forceinline__ uint32_t f2tf32(float f) {
    uint32_t r;
    asm("cvt.rna.tf32.f32 %0, %1;" : "=r"(r) : "f"(f));
    return r;
}

__device__ __forceinline__ void mma_tf32(float* d, const uint32_t* a, const uint32_t* b) {
    asm volatile(
        "mma.sync.aligned.m16n8k8.row.col.f32.tf32.tf32.f32 "
        "{%0,%1,%2,%3}, {%4,%5,%6,%7}, {%8,%9}, {%0,%1,%2,%3};"
        : "+f"(d[0]), "+f"(d[1]), "+f"(d[2]), "+f"(d[3])
        : "r"(a[0]), "r"(a[1]), "r"(a[2]), "r"(a[3]), "r"(b[0]), "r"(b[1]));
}

// ---------------------------------------------------------------------------
// conv1: (B,3,N) -> F[:,0:64], bn + leaky
// ---------------------------------------------------------------------------
__global__ void conv1_kernel(const float* __restrict__ x, const float* __restrict__ W1,
                             const float* __restrict__ g1, const float* __restrict__ b1,
                             float* __restrict__ F) {
    int t = blockIdx.x * blockDim.x + threadIdx.x;
    int o = t & 63;
    int m = t >> 6;
    if (m >= M_ALL) return;
    int b = m >> 12, n = m & 4095;
    const float* xb = x + (size_t)b * 3 * NPTS + n;
    float v = W1[o * 3 + 0] * xb[0] + W1[o * 3 + 1] * xb[NPTS] + W1[o * 3 + 2] * xb[2 * NPTS];
    v = g1[o] * RSQ * v + b1[o];
    F[(size_t)m * 192 + o] = leaky(v);
}

// ---------------------------------------------------------------------------
// norm64: nrm[m] = sum_{c<64} F[m, coff+c]^2
// ---------------------------------------------------------------------------
__global__ void norm64_kernel(const float* __restrict__ F, int coff,
                              float* __restrict__ nrm) {
    int m = blockIdx.x * blockDim.x + threadIdx.x;
    const float4* r = (const float4*)(F + (size_t)m * 192 + coff);
    float s = 0.f;
    #pragma unroll
    for (int i = 0; i < 16; i++) {
        float4 v = r[i];
        s += v.x * v.x + v.y * v.y + v.z * v.z + v.w * v.w;
    }
    nrm[m] = s;
}

// ---------------------------------------------------------------------------
// kNN (round-8 VERBATIM, frozen): tensor-core distance tiles (mma m16n8k8
// tf32, 3xTF32 split) + exact float-key 2-way-parallel register top-k.
// ---------------------------------------------------------------------------
#define KNN_Q_STRIDE 68
#define KNN_C_STRIDE 40
#define KNN_D_STRIDE 36
#define KNN_SMEM_FLOATS (128*KNN_Q_STRIDE*2 + 64*KNN_C_STRIDE*2 + 128*KNN_D_STRIDE + 32)

__global__ void __launch_bounds__(256, 2) knn3_kernel(const float* __restrict__ F, int coff,
                                                      const float* __restrict__ nrm,
                                                      int* __restrict__ idx) {
    extern __shared__ float sm[];
    float* Qhi = sm;                                   // [128][68]
    float* Qlo = Qhi + 128 * KNN_Q_STRIDE;             // [128][68]
    float* Chi = Qlo + 128 * KNN_Q_STRIDE;             // [64][40] k-major
    float* Clo = Chi + 64 * KNN_C_STRIDE;              // [64][40]
    float* Ds  = Clo + 64 * KNN_C_STRIDE;              // [128][36]
    float* scc = Ds + 128 * KNN_D_STRIDE;              // [32]

    int b  = blockIdx.y;
    int m0 = blockIdx.x * 128;
    const float* base = F + (size_t)b * NPTS * 192 + coff;
    const float* nb   = nrm + b * NPTS;
    int tid  = threadIdx.x;
    int lane = tid & 31;
    int warp = tid >> 5;
    int g = lane >> 2, t = lane & 3;
    int grp = tid >> 7;                 // 0/1: candidate half for the scan
    int qid = tid & 127;                // query owned in the scan phase

    // ---- Q tile (128 q x 64 k): load fp32, split hi/lo tf32 planes ----
    #pragma unroll
    for (int it = 0; it < 8; it++) {
        int i  = it * 256 + tid;
        int r  = i & 127;
        int c4 = (i >> 7) << 2;
        float4 v = *(const float4*)&base[(size_t)(m0 + r) * 192 + c4];
        float vv[4] = {v.x, v.y, v.z, v.w};
        #pragma unroll
        for (int j = 0; j < 4; j++) {
            float hi = __uint_as_float(f2tf32(vv[j]));
            Qhi[r * KNN_Q_STRIDE + c4 + j] = hi;
            Qlo[r * KNN_Q_STRIDE + c4 + j] = vv[j] - hi;
        }
    }

    // exact register top-k over this thread's half of candidate space
    float bd[KNN_K]; int bi[KNN_K];
    #pragma unroll
    for (int k = 0; k < KNN_K; k++) { bd[k] = 3.4e38f; bi[k] = 0; }
    float worst = 3.4e38f;

    int qrow0 = 16 * warp + g;          // mma A rows this thread touches
    int qrow1 = qrow0 + 8;

    __syncthreads();

    for (int t0 = 0; t0 < NPTS; t0 += 32) {
        // ---- C tile (32 c x 64 k): transpose to k-major hi/lo planes ----
        #pragma unroll
        for (int it = 0; it < 2; it++) {
            int i  = it * 256 + tid;
            int r  = i & 31;
            int kq = (i >> 5) << 2;
            float4 v = *(const float4*)&base[(size_t)(t0 + r) * 192 + kq];
            float vv[4] = {v.x, v.y, v.z, v.w};
            #pragma unroll
            for (int j = 0; j < 4; j++) {
                float hi = __uint_as_float(f2tf32(vv[j]));
                Chi[(kq + j) * KNN_C_STRIDE + r] = hi;
                Clo[(kq + j) * KNN_C_STRIDE + r] = vv[j] - hi;
            }
        }
        if (tid < 32) scc[tid] = nb[t0 + tid];
        __syncthreads();   // Cs+scc visible; previous scan done (Ds reusable)

        // ---- tensor-core dot products: 4 col-tiles x 8 k-chunks x 3 mma ----
        float acc[4][4];
        #pragma unroll
        for (int ct = 0; ct < 4; ct++)
            #pragma unroll
            for (int j = 0; j < 4; j++) acc[ct][j] = 0.f;

        #pragma unroll
        for (int kc = 0; kc < 8; kc++) {
            int k0 = kc * 8 + t;
            uint32_t ah[4], al[4];
            ah[0] = __float_as_uint(Qhi[qrow0 * KNN_Q_STRIDE + k0]);
            ah[1] = __float_as_uint(Qhi[qrow1 * KNN_Q_STRIDE + k0]);
            ah[2] = __float_as_uint(Qhi[qrow0 * KNN_Q_STRIDE + k0 + 4]);
            ah[3] = __float_as_uint(Qhi[qrow1 * KNN_Q_STRIDE + k0 + 4]);
            al[0] = __float_as_uint(Qlo[qrow0 * KNN_Q_STRIDE + k0]);
            al[1] = __float_as_uint(Qlo[qrow1 * KNN_Q_STRIDE + k0]);
            al[2] = __float_as_uint(Qlo[qrow0 * KNN_Q_STRIDE + k0 + 4]);
            al[3] = __float_as_uint(Qlo[qrow1 * KNN_Q_STRIDE + k0 + 4]);
            #pragma unroll
            for (int ct = 0; ct < 4; ct++) {
                int cc = ct * 8 + g;
                uint32_t bh[2], bl[2];
                bh[0] = __float_as_uint(Chi[k0 * KNN_C_STRIDE + cc]);
                bh[1] = __float_as_uint(Chi[(k0 + 4) * KNN_C_STRIDE + cc]);
                bl[0] = __float_as_uint(Clo[k0 * KNN_C_STRIDE + cc]);
                bl[1] = __float_as_uint(Clo[(k0 + 4) * KNN_C_STRIDE + cc]);
                mma_tf32(acc[ct], ah, bh);
                mma_tf32(acc[ct], ah, bl);
                mma_tf32(acc[ct], al, bh);
            }
        }

        // ---- stage rank keys to Ds: key = cc - 2*dot (exact fp32) ----
        #pragma unroll
        for (int ct = 0; ct < 4; ct++) {
            int c0 = ct * 8 + 2 * t;
            float2 cc2 = *(const float2*)&scc[c0];
            float2 r0v, r1v;
            r0v.x = cc2.x - 2.f * acc[ct][0];
            r0v.y = cc2.y - 2.f * acc[ct][1];
            r1v.x = cc2.x - 2.f * acc[ct][2];
            r1v.y = cc2.y - 2.f * acc[ct][3];
            *(float2*)&Ds[qrow0 * KNN_D_STRIDE + c0] = r0v;
            *(float2*)&Ds[qrow1 * KNN_D_STRIDE + c0] = r1v;
        }
        __syncthreads();   // Ds visible

        // ---- top-k scan: ALL 256 threads, each over 16 of 32 columns ----
        {
            const float4* dr = (const float4*)&Ds[qid * KNN_D_STRIDE + grp * 16];
            int cbase2 = t0 + grp * 16;
            #pragma unroll 2
            for (int j4 = 0; j4 < 4; j4++) {
                float4 v = dr[j4];
                float mn = fminf(fminf(v.x, v.y), fminf(v.z, v.w));
                if (mn < worst) {
                    float dv[4] = {v.x, v.y, v.z, v.w};
                    #pragma unroll
                    for (int l = 0; l < 4; l++) {
                        float td = dv[l];
                        if (td < worst) {
                            int ti = cbase2 + j4 * 4 + l;
                            #pragma unroll
                            for (int p = 0; p < KNN_K; p++) {
                                if (td < bd[p]) {
                                    float tf = bd[p]; bd[p] = td; td = tf;
                                    int t2 = bi[p]; bi[p] = ti; ti = t2;
                                }
                            }
                            worst = bd[KNN_K - 1];
                        }
                    }
                }
            }
        }
    }

    // ---- merge the two per-query lists (exact, tie -> lower index) ----
    __syncthreads();                         // all scans done; smem reusable
    float* sd = Qlo;                         // [128][40] distances
    int*   si = (int*)Qhi;                   // [128][40] indices
    {
        float* pd = &sd[qid * 40 + grp * 20];
        int*   pi = &si[qid * 40 + grp * 20];
        #pragma unroll
        for (int k = 0; k < KNN_K; k++) { pd[k] = bd[k]; pi[k] = bi[k]; }
    }
    __syncthreads();
    if (tid < 128) {
        const float* pd = &sd[tid * 40];
        const int*   pi = &si[tid * 40];
        int* op = idx + (size_t)(b * NPTS + m0 + tid) * KNN_K;
        int p0 = 0, p1 = 0;
        #pragma unroll
        for (int k = 0; k < KNN_K; k++) {
            float d0 = pd[p0], d1 = pd[20 + p1];
            int   i0 = pi[p0], i1 = pi[20 + p1];
            bool take0 = (d0 < d1) || (d0 == d1 && i0 < i1);
            op[k] = take0 ? i0 : i1;
            if (take0) p0++; else p1++;
        }
    }
}

// ---------------------------------------------------------------------------
// gemm_ac: fused edge GEMMs.  A[m,o] = X[m,:64].W[o,:64],
// C[m,o] = X[m,:64].W[o,64:128].  BM=BO=64, BK=16, one X pass.
// ---------------------------------------------------------------------------
__global__ void __launch_bounds__(256) gemm_ac_kernel(
    const float* __restrict__ X, int ldx,
    const float* __restrict__ W,            // [64][128]
    float* __restrict__ A, float* __restrict__ C) {
    __shared__ float Xs[16][68];
    __shared__ float Wa[16][68];
    __shared__ float Wc[16][68];
    int m0 = blockIdx.x * 64;
    int tid = threadIdx.x;
    int tx = tid & 15, ty = tid >> 4;
    float aa[4][4] = {};
    float ac[4][4] = {};
    int r  = tid >> 2;
    int kq = (tid & 3) << 2;
    for (int k0 = 0; k0 < 64; k0 += 16) {
        float4 v  = *(const float4*)&X[(size_t)(m0 + r) * ldx + k0 + kq];
        float4 wa = *(const float4*)&W[(size_t)r * 128 + k0 + kq];
        float4 wc = *(const float4*)&W[(size_t)r * 128 + 64 + k0 + kq];
        Xs[kq + 0][r] = v.x;  Xs[kq + 1][r] = v.y;  Xs[kq + 2][r] = v.z;  Xs[kq + 3][r] = v.w;
        Wa[kq + 0][r] = wa.x; Wa[kq + 1][r] = wa.y; Wa[kq + 2][r] = wa.z; Wa[kq + 3][r] = wa.w;
        Wc[kq + 0][r] = wc.x; Wc[kq + 1][r] = wc.y; Wc[kq + 2][r] = wc.z; Wc[kq + 3][r] = wc.w;
        __syncthreads();
        #pragma unroll
        for (int kk = 0; kk < 16; kk++) {
            float a[4], ba[4], bc[4];
            #pragma unroll
            for (int i = 0; i < 4; i++) a[i] = Xs[kk][ty * 4 + i];
            #pragma unroll
            for (int j = 0; j < 4; j++) { ba[j] = Wa[kk][tx * 4 + j]; bc[j] = Wc[kk][tx * 4 + j]; }
            #pragma unroll
            for (int i = 0; i < 4; i++)
                #pragma unroll
                for (int j = 0; j < 4; j++) {
                    aa[i][j] += a[i] * ba[j];
                    ac[i][j] += a[i] * bc[j];
                }
        }
        __syncthreads();
    }
    #pragma unroll
    for (int i = 0; i < 4; i++) {
        int m = m0 + ty * 4 + i;
        #pragma unroll
        for (int j = 0; j < 4; j++) {
            A[(size_t)m * 64 + tx * 4 + j] = aa[i][j];
            C[(size_t)m * 64 + tx * 4 + j] = ac[i][j];
        }
    }
}

// ---------------------------------------------------------------------------
// gemm128: BM=BO=128, BK=16, 256 threads, 8x8/thread, swizzled smem,
// DOUBLE-BUFFERED: one sync per K-chunk, global prefetch overlapped with
// the FFMA block.  Accumulation order (kk ascending) unchanged.
// ---------------------------------------------------------------------------
__global__ void __launch_bounds__(256) gemm128_kernel(
    const float* __restrict__ X, int ldx,
    const float* __restrict__ W, int ldw,
    float* __restrict__ Y, int ldy, int K,
    const float* __restrict__ g, const float* __restrict__ sh,
    const float* __restrict__ pbias) {
    __shared__ float Xs[2][16 * 128];
    __shared__ float Ws[2][16 * 128];
    int m0 = blockIdx.x * 128, o0 = blockIdx.y * 128;
    int tid = threadIdx.x, tx = tid & 15, ty = tid >> 4;
    float acc[8][8] = {};

    // per-thread load geometry (two load slots: it=0,1)
    int r0g  = tid >> 2;
    int r1g  = (tid + 256) >> 2;
    int c4g  = (tid & 3) << 2;
    int col0 = (((r0g >> 2) ^ (tid & 3)) << 2) | (r0g & 3);
    int col1 = (((r1g >> 2) ^ (tid & 3)) << 2) | (r1g & 3);
    const float* Xp0 = &X[(size_t)(m0 + r0g) * ldx + c4g];
    const float* Xp1 = &X[(size_t)(m0 + r1g) * ldx + c4g];
    const float* Wp0 = &W[(size_t)(o0 + r0g) * ldw + c4g];
    const float* Wp1 = &W[(size_t)(o0 + r1g) * ldw + c4g];

    // preload chunk 0 into buffer 0
    float4 vx0 = *(const float4*)Xp0;
    float4 vx1 = *(const float4*)Xp1;
    float4 vw0 = *(const float4*)Wp0;
    float4 vw1 = *(const float4*)Wp1;
    {
        float* xs = Xs[0]; float* ws = Ws[0];
        xs[(c4g + 0) * 128 + col0] = vx0.x; xs[(c4g + 1) * 128 + col0] = vx0.y;
        xs[(c4g + 2) * 128 + col0] = vx0.z; xs[(c4g + 3) * 128 + col0] = vx0.w;
        xs[(c4g + 0) * 128 + col1] = vx1.x; xs[(c4g + 1) * 128 + col1] = vx1.y;
        xs[(c4g + 2) * 128 + col1] = vx1.z; xs[(c4g + 3) * 128 + col1] = vx1.w;
        ws[(c4g + 0) * 128 + col0] = vw0.x; ws[(c4g + 1) * 128 + col0] = vw0.y;
        ws[(c4g + 2) * 128 + col0] = vw0.z; ws[(c4g + 3) * 128 + col0] = vw0.w;
        ws[(c4g + 0) * 128 + col1] = vw1.x; ws[(c4g + 1) * 128 + col1] = vw1.y;
        ws[(c4g + 2) * 128 + col1] = vw1.z; ws[(c4g + 3) * 128 + col1] = vw1.w;
    }

    int cur = 0;
    for (int k0 = 0; k0 < K; k0 += 16) {
        __syncthreads();               // buf[cur] ready; buf[cur^1] free
        bool has_next = (k0 + 16) < K;
        if (has_next) {                // prefetch next chunk (latency hidden)
            vx0 = *(const float4*)(Xp0 + k0 + 16);
            vx1 = *(const float4*)(Xp1 + k0 + 16);
            vw0 = *(const float4*)(Wp0 + k0 + 16);
            vw1 = *(const float4*)(Wp1 + k0 + 16);
        }
        const float* xs = Xs[cur];
        const float* ws = Ws[cur];
        #pragma unroll
        for (int kk = 0; kk < 16; kk++) {
            int s = (kk >> 2) & 3;
            float4 a0 = *(const float4*)&xs[kk * 128 + (((2 * ty + 0) ^ s) << 2)];
            float4 a1 = *(const float4*)&xs[kk * 128 + (((2 * ty + 1) ^ s) << 2)];
            float4 b0 = *(const float4*)&ws[kk * 128 + (((2 * tx + 0) ^ s) << 2)];
            float4 b1 = *(const float4*)&ws[kk * 128 + (((2 * tx + 1) ^ s) << 2)];
            float a[8]  = {a0.x, a0.y, a0.z, a0.w, a1.x, a1.y, a1.z, a1.w};
            float bb[8] = {b0.x, b0.y, b0.z, b0.w, b1.x, b1.y, b1.z, b1.w};
            #pragma unroll
            for (int i = 0; i < 8; i++)
                #pragma unroll
                for (int j = 0; j < 8; j++)
                    acc[i][j] += a[i] * bb[j];
        }
        if (has_next) {                // store prefetched chunk into free buffer
            float* xs2 = Xs[cur ^ 1]; float* ws2 = Ws[cur ^ 1];
            xs2[(c4g + 0) * 128 + col0] = vx0.x; xs2[(c4g + 1) * 128 + col0] = vx0.y;
            xs2[(c4g + 2) * 128 + col0] = vx0.z; xs2[(c4g + 3) * 128 + col0] = vx0.w;
            xs2[(c4g + 0) * 128 + col1] = vx1.x; xs2[(c4g + 1) * 128 + col1] = vx1.y;
            xs2[(c4g + 2) * 128 + col1] = vx1.z; xs2[(c4g + 3) * 128 + col1] = vx1.w;
            ws2[(c4g + 0) * 128 + col0] = vw0.x; ws2[(c4g + 1) * 128 + col0] = vw0.y;
            ws2[(c4g + 2) * 128 + col0] = vw0.z; ws2[(c4g + 3) * 128 + col0] = vw0.w;
            ws2[(c4g + 0) * 128 + col1] = vw1.x; ws2[(c4g + 1) * 128 + col1] = vw1.y;
            ws2[(c4g + 2) * 128 + col1] = vw1.z; ws2[(c4g + 3) * 128 + col1] = vw1.w;
        }
        cur ^= 1;
    }

    int b = m0 >> 12;
    #pragma unroll
    for (int i = 0; i < 8; i++) {
        int m = m0 + ty * 8 + i;
        #pragma unroll
        for (int j4 = 0; j4 < 8; j4 += 4) {
            float4 o4;
            float* po = (float*)&o4;
            #pragma unroll
            for (int l = 0; l < 4; l++) {
                int o = o0 + tx * 8 + j4 + l;
                float v = acc[i][j4 + l];
                if (pbias) v += pbias[b * ldy + o];
                v = g[o] * RSQ * v + sh[o];
                po[l] = leaky(v);
            }
            *(float4*)&Y[(size_t)m * ldy + o0 + tx * 8 + j4] = o4;
        }
    }
}

// ---------------------------------------------------------------------------
// EdgeConv gather-max
// ---------------------------------------------------------------------------
__global__ void __launch_bounds__(256) edge_max_kernel(
    const float* __restrict__ A, const float* __restrict__ C,
    const int* __restrict__ idx, const float* __restrict__ g,
    const float* __restrict__ sh, float* __restrict__ F, int yoff) {
    int lr = threadIdx.x >> 6;
    int o  = threadIdx.x & 63;
    int m  = blockIdx.x * 4 + lr;
    int b  = m >> 12;
    __shared__ int sj[4][KNN_K];
    if (o < KNN_K) sj[lr][o] = idx[(size_t)m * KNN_K + o];
    __syncthreads();
    float An = A[(size_t)m * 64 + o];
    float Cn = C[(size_t)m * 64 + o];
    float base = Cn - An;
    float s = g[o] * RSQ, shv = sh[o];
    float mx = -3.4e38f;
    const float* Ab = A + ((size_t)(b << 12)) * 64;
    #pragma unroll
    for (int k = 0; k < KNN_K; k++) {
        float v = Ab[(size_t)sj[lr][k] * 64 + o] + base;
        v = leaky(s * v + shv);
        mx = fmaxf(mx, v);
    }
    F[(size_t)m * 192 + yoff + o] = mx;
}

// ---------------------------------------------------------------------------
// Global feature max
// ---------------------------------------------------------------------------
__global__ void init_gmax_kernel(float* __restrict__ gmax) {
    int t = blockIdx.x * blockDim.x + threadIdx.x;
    if (t < BATCH * 1024) gmax[t] = -3.4e38f;
}

__global__ void __launch_bounds__(256) wmax_gemm_kernel(
    const float* __restrict__ F, const float* __restrict__ W6,
    const float* __restrict__ g6, const float* __restrict__ b6,
    float* __restrict__ gmax) {
    __shared__ float Xs[16 * 128];
    __shared__ float Ws[16 * 128];
    __shared__ float sred[16 * 132];
    int b  = blockIdx.z;
    int m0 = blockIdx.x * 128, o0 = blockIdx.y * 128;
    const float* X = F + (size_t)b * NPTS * 192 + 128;   // x3 slice
    int tid = threadIdx.x, tx = tid & 15, ty = tid >> 4;
    float acc[8][8] = {};
    for (int k0 = 0; k0 < 64; k0 += 16) {
        __syncthreads();
        #pragma unroll
        for (int it = 0; it < 2; it++) {
            int i  = tid + it * 256;
            int r  = i >> 2;
            int c4 = (i & 3) << 2;
            int s  = i & 3;
            float4 vx = *(const float4*)&X[(size_t)(m0 + r) * 192 + k0 + c4];
            float4 vw = *(const float4*)&W6[(size_t)(o0 + r) * 64 + k0 + c4];
            int col = (((r >> 2) ^ s) << 2) | (r & 3);
            Xs[(c4 + 0) * 128 + col] = vx.x;
            Xs[(c4 + 1) * 128 + col] = vx.y;
            Xs[(c4 + 2) * 128 + col] = vx.z;
            Xs[(c4 + 3) * 128 + col] = vx.w;
            Ws[(c4 + 0) * 128 + col] = vw.x;
            Ws[(c4 + 1) * 128 + col] = vw.y;
            Ws[(c4 + 2) * 128 + col] = vw.z;
            Ws[(c4 + 3) * 128 + col] = vw.w;
        }
        __syncthreads();
        #pragma unroll
        for (int kk = 0; kk < 16; kk++) {
            int s = (kk >> 2) & 3;
            float4 a0 = *(const float4*)&Xs[kk * 128 + (((2 * ty + 0) ^ s) << 2)];
            float4 a1 = *(const float4*)&Xs[kk * 128 + (((2 * ty + 1) ^ s) << 2)];
            float4 b0 = *(const float4*)&Ws[kk * 128 + (((2 * tx + 0) ^ s) << 2)];
            float4 b1 = *(const float4*)&Ws[kk * 128 + (((2 * tx + 1) ^ s) << 2)];
            float a[8]  = {a0.x, a0.y, a0.z, a0.w, a1.x, a1.y, a1.z, a1.w};
            float bb[8] = {b0.x, b0.y, b0.z, b0.w, b1.x, b1.y, b1.z, b1.w};
            #pragma unroll
            for (int i = 0; i < 8; i++)
                #pragma unroll
                for (int j = 0; j < 8; j++)
                    acc[i][j] += a[i] * bb[j];
        }
    }
    #pragma unroll
    for (int j = 0; j < 8; j++) {
        int o = o0 + tx * 8 + j;
        float s = g6[o] * RSQ, shv = b6[o];
        float mx = -3.4e38f;
        #pragma unroll
        for (int i = 0; i < 8; i++) mx = fmaxf(mx, leaky(s * acc[i][j] + shv));
        sred[ty * 132 + tx * 8 + j] = mx;
    }
    __syncthreads();
    if (tid < 128) {
        float mx = -3.4e38f;
        #pragma unroll
        for (int t = 0; t < 16; t++) mx = fmaxf(mx, sred[t * 132 + tid]);
        atomicMaxF(&gmax[b * 1024 + o0 + tid], mx);
    }
}

// bias7[b,o] = W7[o, 192:1216] . gmax[b,:]
__global__ void bias7_kernel(const float* __restrict__ W7, const float* __restrict__ gmax,
                             float* __restrict__ bias7) {
    int t = blockIdx.x * blockDim.x + threadIdx.x;
    if (t >= BATCH * 512) return;
    int b = t >> 9, o = t & 511;
    const float* w  = W7 + (size_t)o * 1216 + 192;
    const float* gm = gmax + b * 1024;
    float acc = 0.f;
    for (int c = 0; c < 1024; c++) acc += w[c] * gm[c];
    bias7[t] = acc;
}

// ---------------------------------------------------------------------------
// Final: out[b, o, n] = W10[o,:] . x9[m,:] + bias10[o]
// ---------------------------------------------------------------------------
__global__ void final_kernel(const float* __restrict__ X, const float* __restrict__ W10,
                             const float* __restrict__ b10, float* __restrict__ out) {
    int o = threadIdx.x;                       // 0..12
    int m = blockIdx.x * blockDim.y + threadIdx.y;
    const float* xr = X + (size_t)m * 128;
    const float* w  = W10 + (size_t)o * 128;
    float acc = b10[o];
    #pragma unroll
    for (int c = 0; c < 128; c++) acc += w[c] * xr[c];
    int b = m >> 12, n = m & 4095;
    out[((size_t)(b * 13 + o)) * NPTS + n] = acc;
}

// ---------------------------------------------------------------------------
// Launch (idx 3 and idx 7 are knn3 -> ncu capture lands on dominant kernel)
// ---------------------------------------------------------------------------
extern "C" void kernel_launch(void* const* d_in, const int* in_sizes, int n_in,
                              void* d_out, int out_size) {
    const float* x    = (const float*)d_in[0];
    const float* W1   = (const float*)d_in[1];
    const float* g1   = (const float*)d_in[2];
    const float* b1   = (const float*)d_in[3];
    const float* W2   = (const float*)d_in[4];
    const float* g2   = (const float*)d_in[5];
    const float* b2   = (const float*)d_in[6];
    const float* W3   = (const float*)d_in[7];
    const float* g3   = (const float*)d_in[8];
    const float* b3   = (const float*)d_in[9];
    const float* W6   = (const float*)d_in[10];
    const float* g6   = (const float*)d_in[11];
    const float* b6   = (const float*)d_in[12];
    const float* W7   = (const float*)d_in[13];
    const float* g7   = (const float*)d_in[14];
    const float* b7   = (const float*)d_in[15];
    const float* W8   = (const float*)d_in[16];
    const float* g8   = (const float*)d_in[17];
    const float* b8   = (const float*)d_in[18];
    const float* W9   = (const float*)d_in[19];
    const float* g9   = (const float*)d_in[20];
    const float* b9   = (const float*)d_in[21];
    const float* W10  = (const float*)d_in[22];
    const float* b10  = (const float*)d_in[23];
    float* out = (float*)d_out;

    float *F, *A, *C, *nrm, *gmax, *bias7, *buf7, *buf8, *buf9;
    int* idx;
    cudaGetSymbolAddress((void**)&F,     d_F);
    cudaGetSymbolAddress((void**)&A,     d_A);
    cudaGetSymbolAddress((void**)&C,     d_C);
    cudaGetSymbolAddress((void**)&idx,   d_idx);
    cudaGetSymbolAddress((void**)&nrm,   d_nrm);
    cudaGetSymbolAddress((void**)&gmax,  d_gmax);
    cudaGetSymbolAddress((void**)&bias7, d_bias7);
    cudaGetSymbolAddress((void**)&buf7,  d_buf7);
    cudaGetSymbolAddress((void**)&buf8,  d_buf8);
    cudaGetSymbolAddress((void**)&buf9,  d_buf9);

    static int knn_smem = KNN_SMEM_FLOATS * 4;
    cudaFuncSetAttribute(knn3_kernel, cudaFuncAttributeMaxDynamicSharedMemorySize, knn_smem);

    // 0: x1 = leaky(bn(W1 @ x))
    conv1_kernel<<<(M_ALL * 64) / 256, 256>>>(x, W1, g1, b1, F);
    // 1: norms of x1
    norm64_kernel<<<M_ALL / 256, 256>>>(F, 0, nrm);
    // 2: fused A/C edge GEMMs
    gemm_ac_kernel<<<M_ALL / 64, 256>>>(F, 192, W2, A, C);
    // 3  <-- ncu capture candidate
    knn3_kernel<<<dim3(32, BATCH), 256, knn_smem>>>(F, 0, nrm, idx);
    // 4
    edge_max_kernel<<<M_ALL / 4, 256>>>(A, C, idx, g2, b2, F, 64);
    // 5: norms of x2
    norm64_kernel<<<M_ALL / 256, 256>>>(F, 64, nrm);
    // 6
    gemm_ac_kernel<<<M_ALL / 64, 256>>>(F + 64, 192, W3, A, C);
    // 7  <-- ncu capture candidate
    knn3_kernel<<<dim3(32, BATCH), 256, knn_smem>>>(F, 64, nrm, idx);
    // 8
    edge_max_kernel<<<M_ALL / 4, 256>>>(A, C, idx, g3, b3, F, 128);

    // Global feature
    init_gmax_kernel<<<(BATCH * 1024 + 255) / 256, 256>>>(gmax);
    wmax_gemm_kernel<<<dim3(32, 8, BATCH), 256>>>(F, W6, g6, b6, gmax);
    bias7_kernel<<<(BATCH * 512 + 255) / 256, 256>>>(W7, gmax, bias7);

    // MLP head (fp32 SIMT, double-buffered)
    gemm128_kernel<<<dim3(M_ALL / 128, 4), 256>>>(F, 192, W7, 1216, buf7, 512, 192,
                                                  g7, b7, bias7);
    gemm128_kernel<<<dim3(M_ALL / 128, 2), 256>>>(buf7, 512, W8, 512, buf8, 256, 512,
                                                  g8, b8, nullptr);
    gemm128_kernel<<<dim3(M_ALL / 128, 1), 256>>>(buf8, 256, W9, 256, buf9, 128, 256,
                                                  g9, b9, nullptr);
    final_kernel<<<M_ALL / 32, dim3(13, 32)>>>(buf9, W10, b10, out);
}

// round 15
// speedup vs baseline: 1.0085x; 1.0085x over previous
#include <cuda_runtime.h>
#include <cuda_bf16.h>
#include <cstdint>

// ---------------------------------------------------------------------------
// DGCNN segmentation forward.  B=8, C=3, N=4096, K=20, emb=1024, ncls=13.
// Internal layout: row-major (B*N, C) feature matrices.
// ---------------------------------------------------------------------------

#define BATCH 8
#define NPTS  4096
#define M_ALL (BATCH * NPTS)   // 32768
#define KNN_K 20
#define RSQ   0.99999500003749968f   // 1/sqrt(1+1e-5)
#define SLOPE 0.2f

// Scratch (device globals; no allocation allowed)
__device__ float d_F[(size_t)M_ALL * 192];      // [x1 | x2 | x3]
__device__ float d_A[(size_t)M_ALL * 64];
__device__ float d_C[(size_t)M_ALL * 64];
__device__ int   d_idx[(size_t)M_ALL * KNN_K];
__device__ float d_nrm[M_ALL];
__device__ float d_gmax[BATCH * 1024];
__device__ float d_bias7[BATCH * 512];
__device__ float d_buf7[(size_t)M_ALL * 512];
__device__ float d_buf8[(size_t)M_ALL * 256];
__device__ float d_buf9[(size_t)M_ALL * 128];

__device__ __forceinline__ float leaky(float v) { return v > 0.f ? v : SLOPE * v; }

__device__ __forceinline__ void atomicMaxF(float* addr, float v) {
    int* ai = (int*)addr;
    int old = *ai;
    while (__int_as_float(old) < v) {
        int assumed = old;
        old = atomicCAS(ai, assumed, __float_as_int(v));
        if (old == assumed) break;
    }
}

__device__ __forceinline__ uint32_t f2tf32(float f) {
    uint32_t r;
    asm("cvt.rna.tf32.f32 %0, %1;" : "=r"(r) : "f"(f));
    return r;
}

__device__ __forceinline__ void mma_tf32(float* d, const uint32_t* a, const uint32_t* b) {
    asm volatile(
        "mma.sync.aligned.m16n8k8.row.col.f32.tf32.tf32.f32 "
        "{%0,%1,%2,%3}, {%4,%5,%6,%7}, {%8,%9}, {%0,%1,%2,%3};"
        : "+f"(d[0]), "+f"(d[1]), "+f"(d[2]), "+f"(d[3])
        : "r"(a[0]), "r"(a[1]), "r"(a[2]), "r"(a[3]), "r"(b[0]), "r"(b[1]));
}

// ---------------------------------------------------------------------------
// conv1: (B,3,N) -> F[:,0:64], bn + leaky, FUSED x1-norm output.
// Block = 256 thr = 4 points x 64 channels; warp w covers point w>>1,
// channel half w&1 -> shfl reduce + 2-way smem combine per point.
// ---------------------------------------------------------------------------
__global__ void conv1_kernel(const float* __restrict__ x, const float* __restrict__ W1,
                             const float* __restrict__ g1, const float* __restrict__ b1,
                             float* __restrict__ F, float* __restrict__ nrm) {
    __shared__ float part[4][2];
    int t = blockIdx.x * blockDim.x + threadIdx.x;
    int o = t & 63;
    int m = t >> 6;
    int b = m >> 12, n = m & 4095;
    const float* xb = x + (size_t)b * 3 * NPTS + n;
    float v = W1[o * 3 + 0] * xb[0] + W1[o * 3 + 1] * xb[NPTS] + W1[o * 3 + 2] * xb[2 * NPTS];
    v = g1[o] * RSQ * v + b1[o];
    float r = leaky(v);
    F[(size_t)m * 192 + o] = r;
    // fused norm: sum over 64 channels of r^2
    float p = r * r;
    #pragma unroll
    for (int w = 16; w >= 1; w >>= 1) p += __shfl_xor_sync(0xFFFFFFFFu, p, w);
    int warp = threadIdx.x >> 5;
    if ((threadIdx.x & 31) == 0) part[warp >> 1][warp & 1] = p;
    __syncthreads();
    if (threadIdx.x < 4)
        nrm[blockIdx.x * 4 + threadIdx.x] = part[threadIdx.x][0] + part[threadIdx.x][1];
}

// ---------------------------------------------------------------------------
// kNN (round-8 VERBATIM, frozen): tensor-core distance tiles (mma m16n8k8
// tf32, 3xTF32 split) + exact float-key 2-way-parallel register top-k.
// ---------------------------------------------------------------------------
#define KNN_Q_STRIDE 68
#define KNN_C_STRIDE 40
#define KNN_D_STRIDE 36
#define KNN_SMEM_FLOATS (128*KNN_Q_STRIDE*2 + 64*KNN_C_STRIDE*2 + 128*KNN_D_STRIDE + 32)

__global__ void __launch_bounds__(256, 2) knn3_kernel(const float* __restrict__ F, int coff,
                                                      const float* __restrict__ nrm,
                                                      int* __restrict__ idx) {
    extern __shared__ float sm[];
    float* Qhi = sm;                                   // [128][68]
    float* Qlo = Qhi + 128 * KNN_Q_STRIDE;             // [128][68]
    float* Chi = Qlo + 128 * KNN_Q_STRIDE;             // [64][40] k-major
    float* Clo = Chi + 64 * KNN_C_STRIDE;              // [64][40]
    float* Ds  = Clo + 64 * KNN_C_STRIDE;              // [128][36]
    float* scc = Ds + 128 * KNN_D_STRIDE;              // [32]

    int b  = blockIdx.y;
    int m0 = blockIdx.x * 128;
    const float* base = F + (size_t)b * NPTS * 192 + coff;
    const float* nb   = nrm + b * NPTS;
    int tid  = threadIdx.x;
    int lane = tid & 31;
    int warp = tid >> 5;
    int g = lane >> 2, t = lane & 3;
    int grp = tid >> 7;                 // 0/1: candidate half for the scan
    int qid = tid & 127;                // query owned in the scan phase

    // ---- Q tile (128 q x 64 k): load fp32, split hi/lo tf32 planes ----
    #pragma unroll
    for (int it = 0; it < 8; it++) {
        int i  = it * 256 + tid;
        int r  = i & 127;
        int c4 = (i >> 7) << 2;
        float4 v = *(const float4*)&base[(size_t)(m0 + r) * 192 + c4];
        float vv[4] = {v.x, v.y, v.z, v.w};
        #pragma unroll
        for (int j = 0; j < 4; j++) {
            float hi = __uint_as_float(f2tf32(vv[j]));
            Qhi[r * KNN_Q_STRIDE + c4 + j] = hi;
            Qlo[r * KNN_Q_STRIDE + c4 + j] = vv[j] - hi;
        }
    }

    // exact register top-k over this thread's half of candidate space
    float bd[KNN_K]; int bi[KNN_K];
    #pragma unroll
    for (int k = 0; k < KNN_K; k++) { bd[k] = 3.4e38f; bi[k] = 0; }
    float worst = 3.4e38f;

    int qrow0 = 16 * warp + g;          // mma A rows this thread touches
    int qrow1 = qrow0 + 8;

    __syncthreads();

    for (int t0 = 0; t0 < NPTS; t0 += 32) {
        // ---- C tile (32 c x 64 k): transpose to k-major hi/lo planes ----
        #pragma unroll
        for (int it = 0; it < 2; it++) {
            int i  = it * 256 + tid;
            int r  = i & 31;
            int kq = (i >> 5) << 2;
            float4 v = *(const float4*)&base[(size_t)(t0 + r) * 192 + kq];
            float vv[4] = {v.x, v.y, v.z, v.w};
            #pragma unroll
            for (int j = 0; j < 4; j++) {
                float hi = __uint_as_float(f2tf32(vv[j]));
                Chi[(kq + j) * KNN_C_STRIDE + r] = hi;
                Clo[(kq + j) * KNN_C_STRIDE + r] = vv[j] - hi;
            }
        }
        if (tid < 32) scc[tid] = nb[t0 + tid];
        __syncthreads();   // Cs+scc visible; previous scan done (Ds reusable)

        // ---- tensor-core dot products: 4 col-tiles x 8 k-chunks x 3 mma ----
        float acc[4][4];
        #pragma unroll
        for (int ct = 0; ct < 4; ct++)
            #pragma unroll
            for (int j = 0; j < 4; j++) acc[ct][j] = 0.f;

        #pragma unroll
        for (int kc = 0; kc < 8; kc++) {
            int k0 = kc * 8 + t;
            uint32_t ah[4], al[4];
            ah[0] = __float_as_uint(Qhi[qrow0 * KNN_Q_STRIDE + k0]);
            ah[1] = __float_as_uint(Qhi[qrow1 * KNN_Q_STRIDE + k0]);
            ah[2] = __float_as_uint(Qhi[qrow0 * KNN_Q_STRIDE + k0 + 4]);
            ah[3] = __float_as_uint(Qhi[qrow1 * KNN_Q_STRIDE + k0 + 4]);
            al[0] = __float_as_uint(Qlo[qrow0 * KNN_Q_STRIDE + k0]);
            al[1] = __float_as_uint(Qlo[qrow1 * KNN_Q_STRIDE + k0]);
            al[2] = __float_as_uint(Qlo[qrow0 * KNN_Q_STRIDE + k0 + 4]);
            al[3] = __float_as_uint(Qlo[qrow1 * KNN_Q_STRIDE + k0 + 4]);
            #pragma unroll
            for (int ct = 0; ct < 4; ct++) {
                int cc = ct * 8 + g;
                uint32_t bh[2], bl[2];
                bh[0] = __float_as_uint(Chi[k0 * KNN_C_STRIDE + cc]);
                bh[1] = __float_as_uint(Chi[(k0 + 4) * KNN_C_STRIDE + cc]);
                bl[0] = __float_as_uint(Clo[k0 * KNN_C_STRIDE + cc]);
                bl[1] = __float_as_uint(Clo[(k0 + 4) * KNN_C_STRIDE + cc]);
                mma_tf32(acc[ct], ah, bh);
                mma_tf32(acc[ct], ah, bl);
                mma_tf32(acc[ct], al, bh);
            }
        }

        // ---- stage rank keys to Ds: key = cc - 2*dot (exact fp32) ----
        #pragma unroll
        for (int ct = 0; ct < 4; ct++) {
            int c0 = ct * 8 + 2 * t;
            float2 cc2 = *(const float2*)&scc[c0];
            float2 r0v, r1v;
            r0v.x = cc2.x - 2.f * acc[ct][0];
            r0v.y = cc2.y - 2.f * acc[ct][1];
            r1v.x = cc2.x - 2.f * acc[ct][2];
            r1v.y = cc2.y - 2.f * acc[ct][3];
            *(float2*)&Ds[qrow0 * KNN_D_STRIDE + c0] = r0v;
            *(float2*)&Ds[qrow1 * KNN_D_STRIDE + c0] = r1v;
        }
        __syncthreads();   // Ds visible

        // ---- top-k scan: ALL 256 threads, each over 16 of 32 columns ----
        {
            const float4* dr = (const float4*)&Ds[qid * KNN_D_STRIDE + grp * 16];
            int cbase2 = t0 + grp * 16;
            #pragma unroll 2
            for (int j4 = 0; j4 < 4; j4++) {
                float4 v = dr[j4];
                float mn = fminf(fminf(v.x, v.y), fminf(v.z, v.w));
                if (mn < worst) {
                    float dv[4] = {v.x, v.y, v.z, v.w};
                    #pragma unroll
                    for (int l = 0; l < 4; l++) {
                        float td = dv[l];
                        if (td < worst) {
                            int ti = cbase2 + j4 * 4 + l;
                            #pragma unroll
                            for (int p = 0; p < KNN_K; p++) {
                                if (td < bd[p]) {
                                    float tf = bd[p]; bd[p] = td; td = tf;
                                    int t2 = bi[p]; bi[p] = ti; ti = t2;
                                }
                            }
                            worst = bd[KNN_K - 1];
                        }
                    }
                }
            }
        }
    }

    // ---- merge the two per-query lists (exact, tie -> lower index) ----
    __syncthreads();                         // all scans done; smem reusable
    float* sd = Qlo;                         // [128][40] distances
    int*   si = (int*)Qhi;                   // [128][40] indices
    {
        float* pd = &sd[qid * 40 + grp * 20];
        int*   pi = &si[qid * 40 + grp * 20];
        #pragma unroll
        for (int k = 0; k < KNN_K; k++) { pd[k] = bd[k]; pi[k] = bi[k]; }
    }
    __syncthreads();
    if (tid < 128) {
        const float* pd = &sd[tid * 40];
        const int*   pi = &si[tid * 40];
        int* op = idx + (size_t)(b * NPTS + m0 + tid) * KNN_K;
        int p0 = 0, p1 = 0;
        #pragma unroll
        for (int k = 0; k < KNN_K; k++) {
            float d0 = pd[p0], d1 = pd[20 + p1];
            int   i0 = pi[p0], i1 = pi[20 + p1];
            bool take0 = (d0 < d1) || (d0 == d1 && i0 < i1);
            op[k] = take0 ? i0 : i1;
            if (take0) p0++; else p1++;
        }
    }
}

// ---------------------------------------------------------------------------
// gemm_ac: fused edge GEMMs.  A[m,o] = X[m,:64].W[o,:64],
// C[m,o] = X[m,:64].W[o,64:128].  BM=BO=64, BK=16, one X pass.
// ---------------------------------------------------------------------------
__global__ void __launch_bounds__(256) gemm_ac_kernel(
    const float* __restrict__ X, int ldx,
    const float* __restrict__ W,            // [64][128]
    float* __restrict__ A, float* __restrict__ C) {
    __shared__ float Xs[16][68];
    __shared__ float Wa[16][68];
    __shared__ float Wc[16][68];
    int m0 = blockIdx.x * 64;
    int tid = threadIdx.x;
    int tx = tid & 15, ty = tid >> 4;
    float aa[4][4] = {};
    float ac[4][4] = {};
    int r  = tid >> 2;
    int kq = (tid & 3) << 2;
    for (int k0 = 0; k0 < 64; k0 += 16) {
        float4 v  = *(const float4*)&X[(size_t)(m0 + r) * ldx + k0 + kq];
        float4 wa = *(const float4*)&W[(size_t)r * 128 + k0 + kq];
        float4 wc = *(const float4*)&W[(size_t)r * 128 + 64 + k0 + kq];
        Xs[kq + 0][r] = v.x;  Xs[kq + 1][r] = v.y;  Xs[kq + 2][r] = v.z;  Xs[kq + 3][r] = v.w;
        Wa[kq + 0][r] = wa.x; Wa[kq + 1][r] = wa.y; Wa[kq + 2][r] = wa.z; Wa[kq + 3][r] = wa.w;
        Wc[kq + 0][r] = wc.x; Wc[kq + 1][r] = wc.y; Wc[kq + 2][r] = wc.z; Wc[kq + 3][r] = wc.w;
        __syncthreads();
        #pragma unroll
        for (int kk = 0; kk < 16; kk++) {
            float a[4], ba[4], bc[4];
            #pragma unroll
            for (int i = 0; i < 4; i++) a[i] = Xs[kk][ty * 4 + i];
            #pragma unroll
            for (int j = 0; j < 4; j++) { ba[j] = Wa[kk][tx * 4 + j]; bc[j] = Wc[kk][tx * 4 + j]; }
            #pragma unroll
            for (int i = 0; i < 4; i++)
                #pragma unroll
                for (int j = 0; j < 4; j++) {
                    aa[i][j] += a[i] * ba[j];
                    ac[i][j] += a[i] * bc[j];
                }
        }
        __syncthreads();
    }
    #pragma unroll
    for (int i = 0; i < 4; i++) {
        int m = m0 + ty * 4 + i;
        #pragma unroll
        for (int j = 0; j < 4; j++) {
            A[(size_t)m * 64 + tx * 4 + j] = aa[i][j];
            C[(size_t)m * 64 + tx * 4 + j] = ac[i][j];
        }
    }
}

// ---------------------------------------------------------------------------
// gemm128 (round-12 verbatim): BM=BO=128, BK=16, 8x8/thread, swizzled smem.
// ---------------------------------------------------------------------------
__global__ void __launch_bounds__(256) gemm128_kernel(
    const float* __restrict__ X, int ldx,
    const float* __restrict__ W, int ldw,
    float* __restrict__ Y, int ldy, int K,
    const float* __restrict__ g, const float* __restrict__ sh,
    const float* __restrict__ pbias) {
    __shared__ float Xs[16 * 128];
    __shared__ float Ws[16 * 128];
    int m0 = blockIdx.x * 128, o0 = blockIdx.y * 128;
    int tid = threadIdx.x, tx = tid & 15, ty = tid >> 4;
    float acc[8][8] = {};
    for (int k0 = 0; k0 < K; k0 += 16) {
        __syncthreads();
        #pragma unroll
        for (int it = 0; it < 2; it++) {
            int i  = tid + it * 256;
            int r  = i >> 2;
            int c4 = (i & 3) << 2;
            int s  = i & 3;
            float4 vx = *(const float4*)&X[(size_t)(m0 + r) * ldx + k0 + c4];
            float4 vw = *(const float4*)&W[(size_t)(o0 + r) * ldw + k0 + c4];
            int col = (((r >> 2) ^ s) << 2) | (r & 3);
            Xs[(c4 + 0) * 128 + col] = vx.x;
            Xs[(c4 + 1) * 128 + col] = vx.y;
            Xs[(c4 + 2) * 128 + col] = vx.z;
            Xs[(c4 + 3) * 128 + col] = vx.w;
            Ws[(c4 + 0) * 128 + col] = vw.x;
            Ws[(c4 + 1) * 128 + col] = vw.y;
            Ws[(c4 + 2) * 128 + col] = vw.z;
            Ws[(c4 + 3) * 128 + col] = vw.w;
        }
        __syncthreads();
        #pragma unroll
        for (int kk = 0; kk < 16; kk++) {
            int s = (kk >> 2) & 3;
            float4 a0 = *(const float4*)&Xs[kk * 128 + (((2 * ty + 0) ^ s) << 2)];
            float4 a1 = *(const float4*)&Xs[kk * 128 + (((2 * ty + 1) ^ s) << 2)];
            float4 b0 = *(const float4*)&Ws[kk * 128 + (((2 * tx + 0) ^ s) << 2)];
            float4 b1 = *(const float4*)&Ws[kk * 128 + (((2 * tx + 1) ^ s) << 2)];
            float a[8]  = {a0.x, a0.y, a0.z, a0.w, a1.x, a1.y, a1.z, a1.w};
            float bb[8] = {b0.x, b0.y, b0.z, b0.w, b1.x, b1.y, b1.z, b1.w};
            #pragma unroll
            for (int i = 0; i < 8; i++)
                #pragma unroll
                for (int j = 0; j < 8; j++)
                    acc[i][j] += a[i] * bb[j];
        }
    }
    int b = m0 >> 12;
    #pragma unroll
    for (int i = 0; i < 8; i++) {
        int m = m0 + ty * 8 + i;
        #pragma unroll
        for (int j4 = 0; j4 < 8; j4 += 4) {
            float4 o4;
            float* po = (float*)&o4;
            #pragma unroll
            for (int l = 0; l < 4; l++) {
                int o = o0 + tx * 8 + j4 + l;
                float v = acc[i][j4 + l];
                if (pbias) v += pbias[b * ldy + o];
                v = g[o] * RSQ * v + sh[o];
                po[l] = leaky(v);
            }
            *(float4*)&Y[(size_t)m * ldy + o0 + tx * 8 + j4] = o4;
        }
    }
}

// ---------------------------------------------------------------------------
// EdgeConv gather-max, FUSED optional norm of the produced features.
// Block = 256 thr = 4 points x 64 channels; same reduce pattern as conv1.
// ---------------------------------------------------------------------------
__global__ void __launch_bounds__(256) edge_max_kernel(
    const float* __restrict__ A, const float* __restrict__ C,
    const int* __restrict__ idx, const float* __restrict__ g,
    const float* __restrict__ sh, float* __restrict__ F, int yoff,
    float* __restrict__ nrm) {
    int lr = threadIdx.x >> 6;
    int o  = threadIdx.x & 63;
    int m  = blockIdx.x * 4 + lr;
    int b  = m >> 12;
    __shared__ int sj[4][KNN_K];
    __shared__ float part[4][2];
    if (o < KNN_K) sj[lr][o] = idx[(size_t)m * KNN_K + o];
    __syncthreads();
    float An = A[(size_t)m * 64 + o];
    float Cn = C[(size_t)m * 64 + o];
    float base = Cn - An;
    float s = g[o] * RSQ, shv = sh[o];
    float mx = -3.4e38f;
    const float* Ab = A + ((size_t)(b << 12)) * 64;
    #pragma unroll
    for (int k = 0; k < KNN_K; k++) {
        float v = Ab[(size_t)sj[lr][k] * 64 + o] + base;
        v = leaky(s * v + shv);
        mx = fmaxf(mx, v);
    }
    F[(size_t)m * 192 + yoff + o] = mx;
    if (nrm) {
        float p = mx * mx;
        #pragma unroll
        for (int w = 16; w >= 1; w >>= 1) p += __shfl_xor_sync(0xFFFFFFFFu, p, w);
        int warp = threadIdx.x >> 5;
        if ((threadIdx.x & 31) == 0) part[warp >> 1][warp & 1] = p;
        __syncthreads();
        if (threadIdx.x < 4)
            nrm[blockIdx.x * 4 + threadIdx.x] = part[threadIdx.x][0] + part[threadIdx.x][1];
    }
}

// ---------------------------------------------------------------------------
// Global feature max
// ---------------------------------------------------------------------------
__global__ void init_gmax_kernel(float* __restrict__ gmax) {
    int t = blockIdx.x * blockDim.x + threadIdx.x;
    if (t < BATCH * 1024) gmax[t] = -3.4e38f;
}

__global__ void __launch_bounds__(256) wmax_gemm_kernel(
    const float* __restrict__ F, const float* __restrict__ W6,
    const float* __restrict__ g6, const float* __restrict__ b6,
    float* __restrict__ gmax) {
    __shared__ float Xs[16 * 128];
    __shared__ float Ws[16 * 128];
    __shared__ float sred[16 * 132];
    int b  = blockIdx.z;
    int m0 = blockIdx.x * 128, o0 = blockIdx.y * 128;
    const float* X = F + (size_t)b * NPTS * 192 + 128;   // x3 slice
    int tid = threadIdx.x, tx = tid & 15, ty = tid >> 4;
    float acc[8][8] = {};
    for (int k0 = 0; k0 < 64; k0 += 16) {
        __syncthreads();
        #pragma unroll
        for (int it = 0; it < 2; it++) {
            int i  = tid + it * 256;
            int r  = i >> 2;
            int c4 = (i & 3) << 2;
            int s  = i & 3;
            float4 vx = *(const float4*)&X[(size_t)(m0 + r) * 192 + k0 + c4];
            float4 vw = *(const float4*)&W6[(size_t)(o0 + r) * 64 + k0 + c4];
            int col = (((r >> 2) ^ s) << 2) | (r & 3);
            Xs[(c4 + 0) * 128 + col] = vx.x;
            Xs[(c4 + 1) * 128 + col] = vx.y;
            Xs[(c4 + 2) * 128 + col] = vx.z;
            Xs[(c4 + 3) * 128 + col] = vx.w;
            Ws[(c4 + 0) * 128 + col] = vw.x;
            Ws[(c4 + 1) * 128 + col] = vw.y;
            Ws[(c4 + 2) * 128 + col] = vw.z;
            Ws[(c4 + 3) * 128 + col] = vw.w;
        }
        __syncthreads();
        #pragma unroll
        for (int kk = 0; kk < 16; kk++) {
            int s = (kk >> 2) & 3;
            float4 a0 = *(const float4*)&Xs[kk * 128 + (((2 * ty + 0) ^ s) << 2)];
            float4 a1 = *(const float4*)&Xs[kk * 128 + (((2 * ty + 1) ^ s) << 2)];
            float4 b0 = *(const float4*)&Ws[kk * 128 + (((2 * tx + 0) ^ s) << 2)];
            float4 b1 = *(const float4*)&Ws[kk * 128 + (((2 * tx + 1) ^ s) << 2)];
            float a[8]  = {a0.x, a0.y, a0.z, a0.w, a1.x, a1.y, a1.z, a1.w};
            float bb[8] = {b0.x, b0.y, b0.z, b0.w, b1.x, b1.y, b1.z, b1.w};
            #pragma unroll
            for (int i = 0; i < 8; i++)
                #pragma unroll
                for (int j = 0; j < 8; j++)
                    acc[i][j] += a[i] * bb[j];
        }
    }
    #pragma unroll
    for (int j = 0; j < 8; j++) {
        int o = o0 + tx * 8 + j;
        float s = g6[o] * RSQ, shv = b6[o];
        float mx = -3.4e38f;
        #pragma unroll
        for (int i = 0; i < 8; i++) mx = fmaxf(mx, leaky(s * acc[i][j] + shv));
        sred[ty * 132 + tx * 8 + j] = mx;
    }
    __syncthreads();
    if (tid < 128) {
        float mx = -3.4e38f;
        #pragma unroll
        for (int t = 0; t < 16; t++) mx = fmaxf(mx, sred[t * 132 + tid]);
        atomicMaxF(&gmax[b * 1024 + o0 + tid], mx);
    }
}

// bias7[b,o] = W7[o, 192:1216] . gmax[b,:]
__global__ void bias7_kernel(const float* __restrict__ W7, const float* __restrict__ gmax,
                             float* __restrict__ bias7) {
    int t = blockIdx.x * blockDim.x + threadIdx.x;
    if (t >= BATCH * 512) return;
    int b = t >> 9, o = t & 511;
    const float* w  = W7 + (size_t)o * 1216 + 192;
    const float* gm = gmax + b * 1024;
    float acc = 0.f;
    for (int c = 0; c < 1024; c++) acc += w[c] * gm[c];
    bias7[t] = acc;
}

// ---------------------------------------------------------------------------
// Final: out[b, o, n] = W10[o,:] . x9[m,:] + bias10[o]
// ---------------------------------------------------------------------------
__global__ void final_kernel(const float* __restrict__ X, const float* __restrict__ W10,
                             const float* __restrict__ b10, float* __restrict__ out) {
    int o = threadIdx.x;                       // 0..12
    int m = blockIdx.x * blockDim.y + threadIdx.y;
    const float* xr = X + (size_t)m * 128;
    const float* w  = W10 + (size_t)o * 128;
    float acc = b10[o];
    #pragma unroll
    for (int c = 0; c < 128; c++) acc += w[c] * xr[c];
    int b = m >> 12, n = m & 4095;
    out[((size_t)(b * 13 + o)) * NPTS + n] = acc;
}

// ---------------------------------------------------------------------------
// Launch
// ---------------------------------------------------------------------------
extern "C" void kernel_launch(void* const* d_in, const int* in_sizes, int n_in,
                              void* d_out, int out_size) {
    const float* x    = (const float*)d_in[0];
    const float* W1   = (const float*)d_in[1];
    const float* g1   = (const float*)d_in[2];
    const float* b1   = (const float*)d_in[3];
    const float* W2   = (const float*)d_in[4];
    const float* g2   = (const float*)d_in[5];
    const float* b2   = (const float*)d_in[6];
    const float* W3   = (const float*)d_in[7];
    const float* g3   = (const float*)d_in[8];
    const float* b3   = (const float*)d_in[9];
    const float* W6   = (const float*)d_in[10];
    const float* g6   = (const float*)d_in[11];
    const float* b6   = (const float*)d_in[12];
    const float* W7   = (const float*)d_in[13];
    const float* g7   = (const float*)d_in[14];
    const float* b7   = (const float*)d_in[15];
    const float* W8   = (const float*)d_in[16];
    const float* g8   = (const float*)d_in[17];
    const float* b8   = (const float*)d_in[18];
    const float* W9   = (const float*)d_in[19];
    const float* g9   = (const float*)d_in[20];
    const float* b9   = (const float*)d_in[21];
    const float* W10  = (const float*)d_in[22];
    const float* b10  = (const float*)d_in[23];
    float* out = (float*)d_out;

    float *F, *A, *C, *nrm, *gmax, *bias7, *buf7, *buf8, *buf9;
    int* idx;
    cudaGetSymbolAddress((void**)&F,     d_F);
    cudaGetSymbolAddress((void**)&A,     d_A);
    cudaGetSymbolAddress((void**)&C,     d_C);
    cudaGetSymbolAddress((void**)&idx,   d_idx);
    cudaGetSymbolAddress((void**)&nrm,   d_nrm);
    cudaGetSymbolAddress((void**)&gmax,  d_gmax);
    cudaGetSymbolAddress((void**)&bias7, d_bias7);
    cudaGetSymbolAddress((void**)&buf7,  d_buf7);
    cudaGetSymbolAddress((void**)&buf8,  d_buf8);
    cudaGetSymbolAddress((void**)&buf9,  d_buf9);

    static int knn_smem = KNN_SMEM_FLOATS * 4;
    cudaFuncSetAttribute(knn3_kernel, cudaFuncAttributeMaxDynamicSharedMemorySize, knn_smem);

    // 0: x1 = leaky(bn(W1 @ x)) + fused x1-norms
    conv1_kernel<<<(M_ALL * 64) / 256, 256>>>(x, W1, g1, b1, F, nrm);
    // 1: fused A/C edge GEMMs (EdgeConv 1)
    gemm_ac_kernel<<<M_ALL / 64, 256>>>(F, 192, W2, A, C);
    // 2
    knn3_kernel<<<dim3(32, BATCH), 256, knn_smem>>>(F, 0, nrm, idx);
    // 3: gather-max + fused x2-norms
    edge_max_kernel<<<M_ALL / 4, 256>>>(A, C, idx, g2, b2, F, 64, nrm);
    // 4: EdgeConv 2
    gemm_ac_kernel<<<M_ALL / 64, 256>>>(F + 64, 192, W3, A, C);
    // 5
    knn3_kernel<<<dim3(32, BATCH), 256, knn_smem>>>(F, 64, nrm, idx);
    // 6 (no norm needed for x3)
    edge_max_kernel<<<M_ALL / 4, 256>>>(A, C, idx, g3, b3, F, 128, nullptr);

    // Global feature
    init_gmax_kernel<<<(BATCH * 1024 + 255) / 256, 256>>>(gmax);
    wmax_gemm_kernel<<<dim3(32, 8, BATCH), 256>>>(F, W6, g6, b6, gmax);
    bias7_kernel<<<(BATCH * 512 + 255) / 256, 256>>>(W7, gmax, bias7);

    // MLP head (fp32 SIMT, single-buffered — measured fastest)
    gemm128_kernel<<<dim3(M_ALL / 128, 4), 256>>>(F, 192, W7, 1216, buf7, 512, 192,
                                                  g7, b7, bias7);
    gemm128_kernel<<<dim3(M_ALL / 128, 2), 256>>>(buf7, 512, W8, 512, buf8, 256, 512,
                                                  g8, b8, nullptr);
    gemm128_kernel<<<dim3(M_ALL / 128, 1), 256>>>(buf8, 256, W9, 256, buf9, 128, 256,
                                                  g9, b9, nullptr);
    final_kernel<<<M_ALL / 32, dim3(13, 32)>>>(buf9, W10, b10, out);
}